// round 3
// baseline (speedup 1.0000x reference)
#include <cuda_runtime.h>
#include <cstdint>

#define N_NODES 50000
#define N_EDGES 800000
#define D_IN    128
#define D_HID   512
#define D_OUT   128
#define D_CAT   (D_IN + D_HID)

// ---------------- device scratch (no allocations allowed) ----------------
__device__ __align__(16) float g_Z[(size_t)N_NODES * D_HID];     // relu(input @ fc_w + b)
__device__ __align__(16) float g_agg[(size_t)N_NODES * D_HID];   // per-node max-pooled repr
__device__ __align__(16) int   g_counts[N_NODES];
__device__ __align__(16) int   g_offsets[N_NODES + 1];
__device__ __align__(16) int   g_cursor[N_NODES];
__device__ __align__(16) int   g_elist[N_EDGES];                 // targets sorted by src (CSR)
__device__ int g_is64;                                           // adjacency dtype flag

// ---------------- adjacency dtype detection ----------------
// If the buffer is int64 (LE, ids < 50000), every odd int32 word is 0.
// If it's int32, odd words are random node ids (overwhelmingly nonzero).
// Samples stay within the first 1,600,000 int32s -> in-bounds for both layouts.
__global__ void detect_kernel(const int* __restrict__ a) {
    __shared__ int any;
    if (threadIdx.x == 0) any = 0;
    __syncthreads();
    int local = 0;
    for (int i = threadIdx.x; i < 4096; i += 256)
        if (a[2 * i + 1] != 0) local = 1;
    if (local) atomicOr(&any, 1);
    __syncthreads();
    if (threadIdx.x == 0) g_is64 = (any == 0);
}

// ---------------- CSR build ----------------
__global__ void zero_counts_kernel() {
    int i = blockIdx.x * blockDim.x + threadIdx.x;
    if (i < N_NODES) g_counts[i] = 0;
}

__global__ void hist_kernel(const int* __restrict__ adj) {
    int e = blockIdx.x * blockDim.x + threadIdx.x;
    if (e < N_EDGES) {
        int src = g_is64 ? adj[2 * e] : adj[e];
        if ((unsigned)src < (unsigned)N_NODES)
            atomicAdd(&g_counts[src], 1);
    }
}

// single-block exclusive scan over 50000 counts (chunk + Hillis-Steele)
__global__ void scan_kernel() {
    __shared__ int partial[1024];
    const int C = (N_NODES + 1023) / 1024;  // 49
    int t = threadIdx.x;
    int start = t * C;
    int end = start + C;
    if (start > N_NODES) start = N_NODES;
    if (end > N_NODES) end = N_NODES;
    int s = 0;
    for (int i = start; i < end; ++i) s += g_counts[i];
    partial[t] = s;
    __syncthreads();
    for (int off = 1; off < 1024; off <<= 1) {
        int v = (t >= off) ? partial[t - off] : 0;
        __syncthreads();
        partial[t] += v;
        __syncthreads();
    }
    int run = (t == 0) ? 0 : partial[t - 1];
    for (int i = start; i < end; ++i) {
        g_offsets[i] = run;
        g_cursor[i]  = run;
        run += g_counts[i];
    }
    if (t == 1023) g_offsets[N_NODES] = partial[1023];  // total
}

__global__ void scatter_kernel(const int* __restrict__ adj) {
    int e = blockIdx.x * blockDim.x + threadIdx.x;
    if (e < N_EDGES) {
        int is64 = g_is64;
        int src = is64 ? adj[2 * e] : adj[e];
        int trg = is64 ? adj[2 * (N_EDGES + e)] : adj[N_EDGES + e];
        if ((unsigned)src < (unsigned)N_NODES && (unsigned)trg < (unsigned)N_NODES) {
            int pos = atomicAdd(&g_cursor[src], 1);
            if ((unsigned)pos < (unsigned)N_EDGES)
                g_elist[pos] = trg;
        }
    }
}

// ---------------- Z = relu(input @ fc_w + b) ----------------
// M=50000, K=128, N=512. BM=128, BN=64, BK=16, TM=8, TN=4, 256 threads.
__global__ __launch_bounds__(256) void gemm_relu_kernel(
    const float* __restrict__ X, const float* __restrict__ W,
    const float* __restrict__ bias)
{
    __shared__ float As[16][128];
    __shared__ float Bs[16][64];

    const int bm = blockIdx.y * 128;
    const int bn = blockIdx.x * 64;
    const int tid = threadIdx.x;
    const int tn = (tid & 15) * 4;   // 0..60
    const int tm = (tid >> 4) * 8;   // 0..120

    float acc[8][4];
#pragma unroll
    for (int i = 0; i < 8; ++i)
#pragma unroll
        for (int j = 0; j < 4; ++j) acc[i][j] = 0.f;

    for (int k0 = 0; k0 < D_IN; k0 += 16) {
        // A tile: 128 rows x 16 cols = 512 float4, 2 per thread, stored transposed
#pragma unroll
        for (int r = 0; r < 2; ++r) {
            int f = tid + r * 256;
            int row = f >> 2;
            int q = f & 3;
            int gm = bm + row;
            float4 a = make_float4(0.f, 0.f, 0.f, 0.f);
            if (gm < N_NODES)
                a = *(const float4*)(X + (size_t)gm * D_IN + k0 + q * 4);
            As[q * 4 + 0][row] = a.x;
            As[q * 4 + 1][row] = a.y;
            As[q * 4 + 2][row] = a.z;
            As[q * 4 + 3][row] = a.w;
        }
        // B tile: 16 rows x 64 cols = 256 float4, 1 per thread
        {
            int row = tid >> 4;
            int q = tid & 15;
            float4 bv = *(const float4*)(W + (size_t)(k0 + row) * D_HID + bn + q * 4);
            *(float4*)&Bs[row][q * 4] = bv;
        }
        __syncthreads();
#pragma unroll
        for (int k = 0; k < 16; ++k) {
            float4 a0 = *(const float4*)&As[k][tm];
            float4 a1 = *(const float4*)&As[k][tm + 4];
            float4 b0 = *(const float4*)&Bs[k][tn];
            float ar[8] = {a0.x, a0.y, a0.z, a0.w, a1.x, a1.y, a1.z, a1.w};
            float br[4] = {b0.x, b0.y, b0.z, b0.w};
#pragma unroll
            for (int i = 0; i < 8; ++i)
#pragma unroll
                for (int j = 0; j < 4; ++j) acc[i][j] += ar[i] * br[j];
        }
        __syncthreads();
    }

    float bl[4];
#pragma unroll
    for (int j = 0; j < 4; ++j) bl[j] = bias[bn + tn + j];
#pragma unroll
    for (int i = 0; i < 8; ++i) {
        int gm = bm + tm + i;
        if (gm < N_NODES) {
            float4 o;
            o.x = fmaxf(acc[i][0] + bl[0], 0.f);
            o.y = fmaxf(acc[i][1] + bl[1], 0.f);
            o.z = fmaxf(acc[i][2] + bl[2], 0.f);
            o.w = fmaxf(acc[i][3] + bl[3], 0.f);
            *(float4*)(g_Z + (size_t)gm * D_HID + bn + tn) = o;
        }
    }
}

// ---------------- segment max over CSR ----------------
// one block (128 threads) per node; each thread owns one float4 column chunk
__global__ __launch_bounds__(128) void segmax_kernel() {
    int n = blockIdx.x;
    int t = threadIdx.x;
    int beg = g_offsets[n];
    int end = g_offsets[n + 1];

    float4 acc = make_float4(0.f, 0.f, 0.f, 0.f);  // relu >= 0, empty -> 0
    int i = beg;
    for (; i + 1 < end; i += 2) {
        int t1 = g_elist[i];
        int t2 = g_elist[i + 1];
        float4 v1 = *(const float4*)(g_Z + (size_t)t1 * D_HID + t * 4);
        float4 v2 = *(const float4*)(g_Z + (size_t)t2 * D_HID + t * 4);
        acc.x = fmaxf(acc.x, fmaxf(v1.x, v2.x));
        acc.y = fmaxf(acc.y, fmaxf(v1.y, v2.y));
        acc.z = fmaxf(acc.z, fmaxf(v1.z, v2.z));
        acc.w = fmaxf(acc.w, fmaxf(v1.w, v2.w));
    }
    if (i < end) {
        int t1 = g_elist[i];
        float4 v1 = *(const float4*)(g_Z + (size_t)t1 * D_HID + t * 4);
        acc.x = fmaxf(acc.x, v1.x);
        acc.y = fmaxf(acc.y, v1.y);
        acc.z = fmaxf(acc.z, v1.z);
        acc.w = fmaxf(acc.w, v1.w);
    }
    *(float4*)(g_agg + (size_t)n * D_HID + t * 4) = acc;
}

// ---------------- out = [input | agg] @ W ----------------
// M=50000, K=640, N=128. BM=128, BN=128, BK=8, TM=8, TN=8, 256 threads.
__global__ __launch_bounds__(256) void gemm_out_kernel(
    const float* __restrict__ X, const float* __restrict__ W,
    float* __restrict__ out)
{
    __shared__ float As[8][128];
    __shared__ float Bs[8][128];

    const int bm = blockIdx.y * 128;
    const int tid = threadIdx.x;
    const int tn = (tid & 15) * 8;
    const int tm = (tid >> 4) * 8;

    float acc[8][8];
#pragma unroll
    for (int i = 0; i < 8; ++i)
#pragma unroll
        for (int j = 0; j < 8; ++j) acc[i][j] = 0.f;

    for (int k0 = 0; k0 < D_CAT; k0 += 8) {
        // A tile: 128 rows x 8 cols = 256 float4, 1 per thread (concat gather)
        {
            int row = tid >> 1;
            int p = tid & 1;
            int col = k0 + p * 4;
            int gm = bm + row;
            float4 a = make_float4(0.f, 0.f, 0.f, 0.f);
            if (gm < N_NODES) {
                if (col < D_IN)
                    a = *(const float4*)(X + (size_t)gm * D_IN + col);
                else
                    a = *(const float4*)(g_agg + (size_t)gm * D_HID + (col - D_IN));
            }
            As[p * 4 + 0][row] = a.x;
            As[p * 4 + 1][row] = a.y;
            As[p * 4 + 2][row] = a.z;
            As[p * 4 + 3][row] = a.w;
        }
        // B tile: 8 rows x 128 cols = 256 float4, 1 per thread
        {
            int row = tid >> 5;       // 0..7
            int q = tid & 31;         // col/4
            float4 bv = *(const float4*)(W + (size_t)(k0 + row) * D_OUT + q * 4);
            *(float4*)&Bs[row][q * 4] = bv;
        }
        __syncthreads();
#pragma unroll
        for (int k = 0; k < 8; ++k) {
            float4 a0 = *(const float4*)&As[k][tm];
            float4 a1 = *(const float4*)&As[k][tm + 4];
            float4 b0 = *(const float4*)&Bs[k][tn];
            float4 b1 = *(const float4*)&Bs[k][tn + 4];
            float ar[8] = {a0.x, a0.y, a0.z, a0.w, a1.x, a1.y, a1.z, a1.w};
            float br[8] = {b0.x, b0.y, b0.z, b0.w, b1.x, b1.y, b1.z, b1.w};
#pragma unroll
            for (int i = 0; i < 8; ++i)
#pragma unroll
                for (int j = 0; j < 8; ++j) acc[i][j] += ar[i] * br[j];
        }
        __syncthreads();
    }

#pragma unroll
    for (int i = 0; i < 8; ++i) {
        int gm = bm + tm + i;
        if (gm < N_NODES) {
            *(float4*)(out + (size_t)gm * D_OUT + tn)     =
                make_float4(acc[i][0], acc[i][1], acc[i][2], acc[i][3]);
            *(float4*)(out + (size_t)gm * D_OUT + tn + 4) =
                make_float4(acc[i][4], acc[i][5], acc[i][6], acc[i][7]);
        }
    }
}

// ---------------- launch ----------------
extern "C" void kernel_launch(void* const* d_in, const int* in_sizes, int n_in,
                              void* d_out, int out_size) {
    // Resolve inputs by element count (robust to metadata ordering).
    // input: 50000*128=6400000, fc_w: 128*512=65536, fc_b: 512,
    // weights: 640*128=81920, adjacency: 2*800000=1600000
    const float* input = nullptr;
    const float* fc_w  = nullptr;
    const float* fc_b  = nullptr;
    const float* w_out = nullptr;
    const int*   adj   = nullptr;
    for (int i = 0; i < n_in; ++i) {
        switch (in_sizes[i]) {
            case 6400000: input = (const float*)d_in[i]; break;
            case 65536:   fc_w  = (const float*)d_in[i]; break;
            case 512:     fc_b  = (const float*)d_in[i]; break;
            case 81920:   w_out = (const float*)d_in[i]; break;
            case 1600000: adj   = (const int*)d_in[i]; break;
            default: break;
        }
    }
    float* out = (float*)d_out;
    (void)out_size;
    if (!input || !fc_w || !fc_b || !w_out || !adj) return;

    // adjacency dtype detection (int32 vs int64), then CSR build
    detect_kernel<<<1, 256>>>(adj);
    zero_counts_kernel<<<(N_NODES + 255) / 256, 256>>>();
    hist_kernel<<<(N_EDGES + 255) / 256, 256>>>(adj);
    scan_kernel<<<1, 1024>>>();
    scatter_kernel<<<(N_EDGES + 255) / 256, 256>>>(adj);

    // Z = relu(input @ fc_w + b)  (per-node, not per-edge: 16x FLOP reduction)
    dim3 gA(D_HID / 64, (N_NODES + 127) / 128);
    gemm_relu_kernel<<<gA, 256>>>(input, fc_w, fc_b);

    // agg = segment_max(Z[trg], by src)
    segmax_kernel<<<N_NODES, 128>>>();

    // out = [input | agg] @ W
    dim3 gC(1, (N_NODES + 127) / 128);
    gemm_out_kernel<<<gC, 256>>>(input, w_out, out);
}

// round 4
// speedup vs baseline: 1.2280x; 1.2280x over previous
#include <cuda_runtime.h>
#include <cuda_fp16.h>
#include <cstdint>

#define N_NODES 50000
#define N_EDGES 800000
#define D_IN    128
#define D_HID   512
#define D_OUT   128
#define D_CAT   (D_IN + D_HID)
#define SCAN_NB ((N_NODES + 255) / 256)   // 196

// ---------------- device scratch (no allocations allowed) ----------------
__device__ __align__(16) __half g_Zh[(size_t)N_NODES * D_HID];   // relu(x@W+b) in fp16
__device__ __align__(16) float  g_agg[(size_t)N_NODES * D_HID];  // max-pooled repr (fp32)
__device__ __align__(16) int    g_counts[N_NODES];
__device__ __align__(16) int    g_offsets[N_NODES + 1];
__device__ __align__(16) int    g_cursor[N_NODES];
__device__ __align__(16) int    g_elist[N_EDGES];                // targets grouped by src
__device__ __align__(16) int    g_blocksums[256];
__device__ __align__(16) int    g_blockoff[256];
__device__ int g_is64;                                           // adjacency dtype flag

// ---------------- adjacency dtype detection ----------------
// int64 (LE, ids < 50000) -> every odd int32 word is 0. int32 -> odd words are ids.
__global__ void detect_kernel(const int* __restrict__ a) {
    __shared__ int any;
    if (threadIdx.x == 0) any = 0;
    __syncthreads();
    int local = 0;
    for (int i = threadIdx.x; i < 4096; i += 256)
        if (a[2 * i + 1] != 0) local = 1;
    if (local) atomicOr(&any, 1);
    __syncthreads();
    if (threadIdx.x == 0) g_is64 = (any == 0);
}

// ---------------- CSR build ----------------
__global__ void zero_counts_kernel() {
    int i = blockIdx.x * blockDim.x + threadIdx.x;
    if (i < N_NODES) g_counts[i] = 0;
}

__global__ void hist_kernel(const int* __restrict__ adj) {
    int e = blockIdx.x * blockDim.x + threadIdx.x;
    if (e < N_EDGES) {
        int src = g_is64 ? adj[2 * e] : adj[e];
        if ((unsigned)src < (unsigned)N_NODES)
            atomicAdd(&g_counts[src], 1);
    }
}

// stage 1: per-block sums of 256 counts
__global__ __launch_bounds__(256) void blocksum_kernel() {
    __shared__ int sm[256];
    int t = threadIdx.x;
    int i = blockIdx.x * 256 + t;
    int v = (i < N_NODES) ? g_counts[i] : 0;
    sm[t] = v;
    __syncthreads();
    for (int off = 128; off > 0; off >>= 1) {
        if (t < off) sm[t] += sm[t + off];
        __syncthreads();
    }
    if (t == 0) g_blocksums[blockIdx.x] = sm[0];
}

// stage 2: exclusive scan of 196 block sums (single tiny block)
__global__ __launch_bounds__(256) void scanblock_kernel() {
    __shared__ int sm[256];
    int t = threadIdx.x;
    int v = (t < SCAN_NB) ? g_blocksums[t] : 0;
    sm[t] = v;
    __syncthreads();
    for (int off = 1; off < 256; off <<= 1) {
        int x = (t >= off) ? sm[t - off] : 0;
        __syncthreads();
        sm[t] += x;
        __syncthreads();
    }
    if (t < SCAN_NB) g_blockoff[t] = sm[t] - v;   // exclusive
    if (t == 255) g_offsets[N_NODES] = sm[255];   // total
}

// stage 3: per-block exclusive scan + block offset -> offsets & cursor
__global__ __launch_bounds__(256) void offsets_kernel() {
    __shared__ int sm[256];
    int t = threadIdx.x;
    int i = blockIdx.x * 256 + t;
    int v = (i < N_NODES) ? g_counts[i] : 0;
    sm[t] = v;
    __syncthreads();
    for (int off = 1; off < 256; off <<= 1) {
        int x = (t >= off) ? sm[t - off] : 0;
        __syncthreads();
        sm[t] += x;
        __syncthreads();
    }
    if (i < N_NODES) {
        int excl = g_blockoff[blockIdx.x] + sm[t] - v;
        g_offsets[i] = excl;
        g_cursor[i]  = excl;
    }
}

__global__ void scatter_kernel(const int* __restrict__ adj) {
    int e = blockIdx.x * blockDim.x + threadIdx.x;
    if (e < N_EDGES) {
        int is64 = g_is64;
        int src = is64 ? adj[2 * e] : adj[e];
        int trg = is64 ? adj[2 * (N_EDGES + e)] : adj[N_EDGES + e];
        if ((unsigned)src < (unsigned)N_NODES && (unsigned)trg < (unsigned)N_NODES) {
            int pos = atomicAdd(&g_cursor[src], 1);
            if ((unsigned)pos < (unsigned)N_EDGES)
                g_elist[pos] = trg;
        }
    }
}

// ---------------- Z = relu(input @ fc_w + b) -> fp16 ----------------
// M=50000, K=128, N=512. BM=128, BN=128, BK=8, TM=8, TN=8, 256 threads.
__global__ __launch_bounds__(256) void gemm_relu_kernel(
    const float* __restrict__ X, const float* __restrict__ W,
    const float* __restrict__ bias)
{
    __shared__ float As[8][128];
    __shared__ float Bs[8][128];

    const int bm = blockIdx.y * 128;
    const int bn = blockIdx.x * 128;
    const int tid = threadIdx.x;
    const int tn = (tid & 15) * 8;
    const int tm = (tid >> 4) * 8;

    float acc[8][8];
#pragma unroll
    for (int i = 0; i < 8; ++i)
#pragma unroll
        for (int j = 0; j < 8; ++j) acc[i][j] = 0.f;

    for (int k0 = 0; k0 < D_IN; k0 += 8) {
        // A tile: 128 rows x 8 cols = 256 float4, stored transposed
        {
            int row = tid >> 1;
            int p = tid & 1;
            int col = k0 + p * 4;
            int gm = bm + row;
            float4 a = make_float4(0.f, 0.f, 0.f, 0.f);
            if (gm < N_NODES)
                a = *(const float4*)(X + (size_t)gm * D_IN + col);
            As[p * 4 + 0][row] = a.x;
            As[p * 4 + 1][row] = a.y;
            As[p * 4 + 2][row] = a.z;
            As[p * 4 + 3][row] = a.w;
        }
        // B tile: 8 rows x 128 cols
        {
            int row = tid >> 5;
            int q = tid & 31;
            float4 bv = *(const float4*)(W + (size_t)(k0 + row) * D_HID + bn + q * 4);
            *(float4*)&Bs[row][q * 4] = bv;
        }
        __syncthreads();
#pragma unroll
        for (int k = 0; k < 8; ++k) {
            float4 a0 = *(const float4*)&As[k][tm];
            float4 a1 = *(const float4*)&As[k][tm + 4];
            float4 b0 = *(const float4*)&Bs[k][tn];
            float4 b1 = *(const float4*)&Bs[k][tn + 4];
            float ar[8] = {a0.x, a0.y, a0.z, a0.w, a1.x, a1.y, a1.z, a1.w};
            float br[8] = {b0.x, b0.y, b0.z, b0.w, b1.x, b1.y, b1.z, b1.w};
#pragma unroll
            for (int i = 0; i < 8; ++i)
#pragma unroll
                for (int j = 0; j < 8; ++j) acc[i][j] += ar[i] * br[j];
        }
        __syncthreads();
    }

    float bl[8];
#pragma unroll
    for (int j = 0; j < 8; ++j) bl[j] = bias[bn + tn + j];

#pragma unroll
    for (int i = 0; i < 8; ++i) {
        int gm = bm + tm + i;
        if (gm < N_NODES) {
            union { __half h[8]; uint4 u; } pk;
#pragma unroll
            for (int j = 0; j < 8; ++j)
                pk.h[j] = __float2half_rn(fmaxf(acc[i][j] + bl[j], 0.f));
            *(uint4*)(g_Zh + (size_t)gm * D_HID + bn + tn) = pk.u;
        }
    }
}

// ---------------- segment max over CSR (fp16 gather, fp32 out) ----------------
// one block (128 threads) per node; thread t owns cols [4t, 4t+4)
__global__ __launch_bounds__(128) void segmax_kernel() {
    int n = blockIdx.x;
    int t = threadIdx.x;
    int beg = g_offsets[n];
    int end = g_offsets[n + 1];

    __half2 m0 = __float2half2_rn(0.f);  // relu >= 0, empty -> 0
    __half2 m1 = __float2half2_rn(0.f);

    int i = beg;
    for (; i + 3 < end; i += 4) {
        int e0 = g_elist[i + 0];
        int e1 = g_elist[i + 1];
        int e2 = g_elist[i + 2];
        int e3 = g_elist[i + 3];
        uint2 v0 = *(const uint2*)(g_Zh + (size_t)e0 * D_HID + t * 4);
        uint2 v1 = *(const uint2*)(g_Zh + (size_t)e1 * D_HID + t * 4);
        uint2 v2 = *(const uint2*)(g_Zh + (size_t)e2 * D_HID + t * 4);
        uint2 v3 = *(const uint2*)(g_Zh + (size_t)e3 * D_HID + t * 4);
        m0 = __hmax2(m0, *(const __half2*)&v0.x);
        m1 = __hmax2(m1, *(const __half2*)&v0.y);
        m0 = __hmax2(m0, *(const __half2*)&v1.x);
        m1 = __hmax2(m1, *(const __half2*)&v1.y);
        m0 = __hmax2(m0, *(const __half2*)&v2.x);
        m1 = __hmax2(m1, *(const __half2*)&v2.y);
        m0 = __hmax2(m0, *(const __half2*)&v3.x);
        m1 = __hmax2(m1, *(const __half2*)&v3.y);
    }
    for (; i < end; ++i) {
        int e0 = g_elist[i];
        uint2 v0 = *(const uint2*)(g_Zh + (size_t)e0 * D_HID + t * 4);
        m0 = __hmax2(m0, *(const __half2*)&v0.x);
        m1 = __hmax2(m1, *(const __half2*)&v0.y);
    }

    float2 f0 = __half22float2(m0);
    float2 f1 = __half22float2(m1);
    *(float4*)(g_agg + (size_t)n * D_HID + t * 4) =
        make_float4(f0.x, f0.y, f1.x, f1.y);
}

// ---------------- out = [input | agg] @ W ----------------
// M=50000, K=640, N=128. BM=128, BN=128, BK=8, TM=8, TN=8, 256 threads.
__global__ __launch_bounds__(256) void gemm_out_kernel(
    const float* __restrict__ X, const float* __restrict__ W,
    float* __restrict__ out)
{
    __shared__ float As[8][128];
    __shared__ float Bs[8][128];

    const int bm = blockIdx.y * 128;
    const int tid = threadIdx.x;
    const int tn = (tid & 15) * 8;
    const int tm = (tid >> 4) * 8;

    float acc[8][8];
#pragma unroll
    for (int i = 0; i < 8; ++i)
#pragma unroll
        for (int j = 0; j < 8; ++j) acc[i][j] = 0.f;

    for (int k0 = 0; k0 < D_CAT; k0 += 8) {
        {
            int row = tid >> 1;
            int p = tid & 1;
            int col = k0 + p * 4;
            int gm = bm + row;
            float4 a = make_float4(0.f, 0.f, 0.f, 0.f);
            if (gm < N_NODES) {
                if (col < D_IN)
                    a = *(const float4*)(X + (size_t)gm * D_IN + col);
                else
                    a = *(const float4*)(g_agg + (size_t)gm * D_HID + (col - D_IN));
            }
            As[p * 4 + 0][row] = a.x;
            As[p * 4 + 1][row] = a.y;
            As[p * 4 + 2][row] = a.z;
            As[p * 4 + 3][row] = a.w;
        }
        {
            int row = tid >> 5;
            int q = tid & 31;
            float4 bv = *(const float4*)(W + (size_t)(k0 + row) * D_OUT + q * 4);
            *(float4*)&Bs[row][q * 4] = bv;
        }
        __syncthreads();
#pragma unroll
        for (int k = 0; k < 8; ++k) {
            float4 a0 = *(const float4*)&As[k][tm];
            float4 a1 = *(const float4*)&As[k][tm + 4];
            float4 b0 = *(const float4*)&Bs[k][tn];
            float4 b1 = *(const float4*)&Bs[k][tn + 4];
            float ar[8] = {a0.x, a0.y, a0.z, a0.w, a1.x, a1.y, a1.z, a1.w};
            float br[8] = {b0.x, b0.y, b0.z, b0.w, b1.x, b1.y, b1.z, b1.w};
#pragma unroll
            for (int i = 0; i < 8; ++i)
#pragma unroll
                for (int j = 0; j < 8; ++j) acc[i][j] += ar[i] * br[j];
        }
        __syncthreads();
    }

#pragma unroll
    for (int i = 0; i < 8; ++i) {
        int gm = bm + tm + i;
        if (gm < N_NODES) {
            *(float4*)(out + (size_t)gm * D_OUT + tn)     =
                make_float4(acc[i][0], acc[i][1], acc[i][2], acc[i][3]);
            *(float4*)(out + (size_t)gm * D_OUT + tn + 4) =
                make_float4(acc[i][4], acc[i][5], acc[i][6], acc[i][7]);
        }
    }
}

// ---------------- launch ----------------
extern "C" void kernel_launch(void* const* d_in, const int* in_sizes, int n_in,
                              void* d_out, int out_size) {
    const float* input = nullptr;
    const float* fc_w  = nullptr;
    const float* fc_b  = nullptr;
    const float* w_out = nullptr;
    const int*   adj   = nullptr;
    for (int i = 0; i < n_in; ++i) {
        switch (in_sizes[i]) {
            case 6400000: input = (const float*)d_in[i]; break;
            case 65536:   fc_w  = (const float*)d_in[i]; break;
            case 512:     fc_b  = (const float*)d_in[i]; break;
            case 81920:   w_out = (const float*)d_in[i]; break;
            case 1600000: adj   = (const int*)d_in[i]; break;
            default: break;
        }
    }
    float* out = (float*)d_out;
    (void)out_size;
    if (!input || !fc_w || !fc_b || !w_out || !adj) return;

    // adjacency dtype detection, then CSR build (multi-block scan)
    detect_kernel<<<1, 256>>>(adj);
    zero_counts_kernel<<<(N_NODES + 255) / 256, 256>>>();
    hist_kernel<<<(N_EDGES + 255) / 256, 256>>>(adj);
    blocksum_kernel<<<SCAN_NB, 256>>>();
    scanblock_kernel<<<1, 256>>>();
    offsets_kernel<<<SCAN_NB, 256>>>();
    scatter_kernel<<<(N_EDGES + 255) / 256, 256>>>(adj);

    // Z = relu(input @ fc_w + b) -> fp16 (per-node, 16x FLOP cut vs per-edge)
    dim3 gA(D_HID / 128, (N_NODES + 127) / 128);
    gemm_relu_kernel<<<gA, 256>>>(input, fc_w, fc_b);

    // agg = segment_max(Z[trg], by src)
    segmax_kernel<<<N_NODES, 128>>>();

    // out = [input | agg] @ W
    dim3 gC(1, (N_NODES + 127) / 128);
    gemm_out_kernel<<<gC, 256>>>(input, w_out, out);
}

// round 5
// speedup vs baseline: 3.0274x; 2.4654x over previous
#include <cuda_runtime.h>
#include <cuda_fp16.h>
#include <mma.h>
#include <cstdint>

using namespace nvcuda;

#define N_NODES 50000
#define N_EDGES 800000
#define D_IN    128
#define D_HID   512
#define D_OUT   128
#define D_CAT   (D_IN + D_HID)
#define SCAN_NB ((N_NODES + 255) / 256)   // 196

// ---------------- device scratch (no allocations allowed) ----------------
__device__ __align__(16) __half g_Zh[(size_t)N_NODES * D_HID];   // relu(x@W+b) fp16
__device__ __align__(16) __half g_cat[(size_t)N_NODES * D_CAT];  // [Xh | agg_h]
__device__ __align__(16) __half g_Wh[(size_t)D_IN * D_HID];      // fc_w fp16
__device__ __align__(16) __half g_W2h[(size_t)D_CAT * D_OUT];    // weights fp16
__device__ __align__(16) int    g_counts[N_NODES];
__device__ __align__(16) int    g_offsets[N_NODES + 1];
__device__ __align__(16) int    g_cursor[N_NODES];
__device__ __align__(16) int    g_elist[N_EDGES];
__device__ __align__(16) int    g_blocksums[256];
__device__ __align__(16) int    g_blockoff[256];
__device__ int g_is64;

// ---------------- adjacency dtype detection ----------------
__global__ void detect_kernel(const int* __restrict__ a) {
    __shared__ int any;
    if (threadIdx.x == 0) any = 0;
    __syncthreads();
    int local = 0;
    for (int i = threadIdx.x; i < 4096; i += 256)
        if (a[2 * i + 1] != 0) local = 1;
    if (local) atomicOr(&any, 1);
    __syncthreads();
    if (threadIdx.x == 0) g_is64 = (any == 0);
}

// ---------------- CSR build ----------------
__global__ void zero_counts_kernel() {
    int i = blockIdx.x * blockDim.x + threadIdx.x;
    if (i < N_NODES) g_counts[i] = 0;
}

__global__ void hist_kernel(const int* __restrict__ adj) {
    int e = blockIdx.x * blockDim.x + threadIdx.x;
    if (e < N_EDGES) {
        int src = g_is64 ? adj[2 * e] : adj[e];
        if ((unsigned)src < (unsigned)N_NODES)
            atomicAdd(&g_counts[src], 1);
    }
}

__global__ __launch_bounds__(256) void blocksum_kernel() {
    __shared__ int sm[256];
    int t = threadIdx.x;
    int i = blockIdx.x * 256 + t;
    sm[t] = (i < N_NODES) ? g_counts[i] : 0;
    __syncthreads();
    for (int off = 128; off > 0; off >>= 1) {
        if (t < off) sm[t] += sm[t + off];
        __syncthreads();
    }
    if (t == 0) g_blocksums[blockIdx.x] = sm[0];
}

__global__ __launch_bounds__(256) void scanblock_kernel() {
    __shared__ int sm[256];
    int t = threadIdx.x;
    int v = (t < SCAN_NB) ? g_blocksums[t] : 0;
    sm[t] = v;
    __syncthreads();
    for (int off = 1; off < 256; off <<= 1) {
        int x = (t >= off) ? sm[t - off] : 0;
        __syncthreads();
        sm[t] += x;
        __syncthreads();
    }
    if (t < SCAN_NB) g_blockoff[t] = sm[t] - v;
    if (t == 255) g_offsets[N_NODES] = sm[255];
}

__global__ __launch_bounds__(256) void offsets_kernel() {
    __shared__ int sm[256];
    int t = threadIdx.x;
    int i = blockIdx.x * 256 + t;
    int v = (i < N_NODES) ? g_counts[i] : 0;
    sm[t] = v;
    __syncthreads();
    for (int off = 1; off < 256; off <<= 1) {
        int x = (t >= off) ? sm[t - off] : 0;
        __syncthreads();
        sm[t] += x;
        __syncthreads();
    }
    if (i < N_NODES) {
        int excl = g_blockoff[blockIdx.x] + sm[t] - v;
        g_offsets[i] = excl;
        g_cursor[i]  = excl;
    }
}

__global__ void scatter_kernel(const int* __restrict__ adj) {
    int e = blockIdx.x * blockDim.x + threadIdx.x;
    if (e < N_EDGES) {
        int is64 = g_is64;
        int src = is64 ? adj[2 * e] : adj[e];
        int trg = is64 ? adj[2 * (N_EDGES + e)] : adj[N_EDGES + e];
        if ((unsigned)src < (unsigned)N_NODES && (unsigned)trg < (unsigned)N_NODES) {
            int pos = atomicAdd(&g_cursor[src], 1);
            if ((unsigned)pos < (unsigned)N_EDGES)
                g_elist[pos] = trg;
        }
    }
}

// ---------------- conversions to fp16 ----------------
// X -> g_cat[:, 0:128]
__global__ void conv_x_kernel(const float* __restrict__ X) {
    int idx = blockIdx.x * blockDim.x + threadIdx.x;   // one uint4 (8 halves)
    if (idx >= (N_NODES * D_IN) / 8) return;
    int i = idx * 8;
    int row = i >> 7;
    int col = i & 127;
    float4 a = *(const float4*)(X + i);
    float4 b = *(const float4*)(X + i + 4);
    union { __half h[8]; uint4 u; } pk;
    pk.h[0] = __float2half_rn(a.x); pk.h[1] = __float2half_rn(a.y);
    pk.h[2] = __float2half_rn(a.z); pk.h[3] = __float2half_rn(a.w);
    pk.h[4] = __float2half_rn(b.x); pk.h[5] = __float2half_rn(b.y);
    pk.h[6] = __float2half_rn(b.z); pk.h[7] = __float2half_rn(b.w);
    *(uint4*)(g_cat + (size_t)row * D_CAT + col) = pk.u;
}

__global__ void conv_w_kernel(const float* __restrict__ fcw, const float* __restrict__ w2) {
    int i = blockIdx.x * blockDim.x + threadIdx.x;
    if (i < D_IN * D_HID) g_Wh[i] = __float2half_rn(fcw[i]);
    if (i < D_CAT * D_OUT) g_W2h[i] = __float2half_rn(w2[i]);
}

// ---------------- Z = relu(Xh @ Wh + b) via wmma -> fp16 ----------------
// BM=128, BN=64, BK=32, 8 warps as 4(M)x2(N), warp tile 32x32.
__global__ __launch_bounds__(256) void gemm_relu_wmma(const float* __restrict__ bias) {
    __shared__ union SMem {
        struct { __half A[128 * 40]; __half B[32 * 72]; } t;
        float C[8 * 32 * 36];
    } sm;

    const int bm = blockIdx.y * 128;
    const int bn = blockIdx.x * 64;
    const int tid = threadIdx.x;
    const int warp = tid >> 5;
    const int lane = tid & 31;
    const int wm = warp >> 1;     // 0..3
    const int wn = warp & 1;      // 0..1

    wmma::fragment<wmma::accumulator, 16, 16, 16, float> acc[2][2];
#pragma unroll
    for (int i = 0; i < 2; ++i)
#pragma unroll
        for (int j = 0; j < 2; ++j) wmma::fill_fragment(acc[i][j], 0.f);

    for (int k0 = 0; k0 < D_IN; k0 += 32) {
#pragma unroll
        for (int r = 0; r < 2; ++r) {
            int f = tid + r * 256;
            int row = f >> 2, seg = f & 3;
            int gr = bm + row; if (gr >= N_NODES) gr = N_NODES - 1;
            *(uint4*)&sm.t.A[row * 40 + seg * 8] =
                *(const uint4*)(g_cat + (size_t)gr * D_CAT + k0 + seg * 8);
        }
        {
            int row = tid >> 3, seg = tid & 7;
            *(uint4*)&sm.t.B[row * 72 + seg * 8] =
                *(const uint4*)(g_Wh + (size_t)(k0 + row) * D_HID + bn + seg * 8);
        }
        __syncthreads();
#pragma unroll
        for (int kk = 0; kk < 2; ++kk) {
            wmma::fragment<wmma::matrix_a, 16, 16, 16, __half, wmma::row_major> af[2];
            wmma::fragment<wmma::matrix_b, 16, 16, 16, __half, wmma::row_major> bf[2];
#pragma unroll
            for (int i = 0; i < 2; ++i)
                wmma::load_matrix_sync(af[i], &sm.t.A[(wm * 32 + i * 16) * 40 + kk * 16], 40);
#pragma unroll
            for (int j = 0; j < 2; ++j)
                wmma::load_matrix_sync(bf[j], &sm.t.B[(kk * 16) * 72 + wn * 32 + j * 16], 72);
#pragma unroll
            for (int i = 0; i < 2; ++i)
#pragma unroll
                for (int j = 0; j < 2; ++j)
                    wmma::mma_sync(acc[i][j], af[i], bf[j], acc[i][j]);
        }
        __syncthreads();
    }

    // epilogue via per-warp smem staging
    float* cw = &sm.C[warp * 32 * 36];
#pragma unroll
    for (int i = 0; i < 2; ++i)
#pragma unroll
        for (int j = 0; j < 2; ++j)
            wmma::store_matrix_sync(&cw[(i * 16) * 36 + j * 16], acc[i][j], 36, wmma::mem_row_major);
    __syncwarp();

    int r = lane;                 // row within warp tile
    int gr = bm + wm * 32 + r;
    if (gr < N_NODES) {
        int cbase = bn + wn * 32;
        union { __half h[8]; uint4 u; } pk;
#pragma unroll
        for (int q = 0; q < 4; ++q) {          // 4 x 8 halves = 32 cols
#pragma unroll
            for (int c = 0; c < 8; ++c) {
                int col = q * 8 + c;
                float v = cw[r * 36 + col] + bias[cbase + col];
                pk.h[c] = __float2half_rn(fmaxf(v, 0.f));
            }
            *(uint4*)(g_Zh + (size_t)gr * D_HID + cbase + q * 8) = pk.u;
        }
    }
}

// ---------------- segment max over CSR -> fp16 into g_cat[:,128:640] ----------------
__global__ __launch_bounds__(128) void segmax_kernel() {
    int n = blockIdx.x;
    int t = threadIdx.x;
    int beg = g_offsets[n];
    int end = g_offsets[n + 1];

    __half2 m0 = __float2half2_rn(0.f);
    __half2 m1 = __float2half2_rn(0.f);

    int i = beg;
    for (; i + 3 < end; i += 4) {
        int e0 = g_elist[i + 0];
        int e1 = g_elist[i + 1];
        int e2 = g_elist[i + 2];
        int e3 = g_elist[i + 3];
        uint2 v0 = *(const uint2*)(g_Zh + (size_t)e0 * D_HID + t * 4);
        uint2 v1 = *(const uint2*)(g_Zh + (size_t)e1 * D_HID + t * 4);
        uint2 v2 = *(const uint2*)(g_Zh + (size_t)e2 * D_HID + t * 4);
        uint2 v3 = *(const uint2*)(g_Zh + (size_t)e3 * D_HID + t * 4);
        m0 = __hmax2(m0, *(const __half2*)&v0.x);
        m1 = __hmax2(m1, *(const __half2*)&v0.y);
        m0 = __hmax2(m0, *(const __half2*)&v1.x);
        m1 = __hmax2(m1, *(const __half2*)&v1.y);
        m0 = __hmax2(m0, *(const __half2*)&v2.x);
        m1 = __hmax2(m1, *(const __half2*)&v2.y);
        m0 = __hmax2(m0, *(const __half2*)&v3.x);
        m1 = __hmax2(m1, *(const __half2*)&v3.y);
    }
    for (; i < end; ++i) {
        int e0 = g_elist[i];
        uint2 v0 = *(const uint2*)(g_Zh + (size_t)e0 * D_HID + t * 4);
        m0 = __hmax2(m0, *(const __half2*)&v0.x);
        m1 = __hmax2(m1, *(const __half2*)&v0.y);
    }

    uint2 o;
    *(__half2*)&o.x = m0;
    *(__half2*)&o.y = m1;
    *(uint2*)(g_cat + (size_t)n * D_CAT + D_IN + t * 4) = o;
}

// ---------------- out = g_cat @ W2h via wmma (fp32 out) ----------------
// BM=128, BN=128, BK=32, 8 warps 4(M)x2(N), warp tile 32x64.
__global__ __launch_bounds__(256) void gemm_out_wmma(float* __restrict__ out) {
    __shared__ __half As[128 * 40];
    __shared__ __half Bs[32 * 136];

    const int bm = blockIdx.x * 128;
    const int tid = threadIdx.x;
    const int warp = tid >> 5;
    const int wm = warp >> 1;     // 0..3
    const int wn = warp & 1;      // 0..1

    wmma::fragment<wmma::accumulator, 16, 16, 16, float> acc[2][4];
#pragma unroll
    for (int i = 0; i < 2; ++i)
#pragma unroll
        for (int j = 0; j < 4; ++j) wmma::fill_fragment(acc[i][j], 0.f);

    for (int k0 = 0; k0 < D_CAT; k0 += 32) {
#pragma unroll
        for (int r = 0; r < 2; ++r) {
            int f = tid + r * 256;
            int row = f >> 2, seg = f & 3;
            int gr = bm + row; if (gr >= N_NODES) gr = N_NODES - 1;
            *(uint4*)&As[row * 40 + seg * 8] =
                *(const uint4*)(g_cat + (size_t)gr * D_CAT + k0 + seg * 8);
        }
#pragma unroll
        for (int r = 0; r < 2; ++r) {
            int f = tid + r * 256;
            int row = f >> 4, seg = f & 15;
            *(uint4*)&Bs[row * 136 + seg * 8] =
                *(const uint4*)(g_W2h + (size_t)(k0 + row) * D_OUT + seg * 8);
        }
        __syncthreads();
#pragma unroll
        for (int kk = 0; kk < 2; ++kk) {
            wmma::fragment<wmma::matrix_a, 16, 16, 16, __half, wmma::row_major> af[2];
            wmma::fragment<wmma::matrix_b, 16, 16, 16, __half, wmma::row_major> bf[4];
#pragma unroll
            for (int i = 0; i < 2; ++i)
                wmma::load_matrix_sync(af[i], &As[(wm * 32 + i * 16) * 40 + kk * 16], 40);
#pragma unroll
            for (int j = 0; j < 4; ++j)
                wmma::load_matrix_sync(bf[j], &Bs[(kk * 16) * 136 + wn * 64 + j * 16], 136);
#pragma unroll
            for (int i = 0; i < 2; ++i)
#pragma unroll
                for (int j = 0; j < 4; ++j)
                    wmma::mma_sync(acc[i][j], af[i], bf[j], acc[i][j]);
        }
        __syncthreads();
    }

    // direct store; 50000 % 16 == 0 so per-frag guard is exact
#pragma unroll
    for (int i = 0; i < 2; ++i) {
        int gr0 = bm + wm * 32 + i * 16;
        if (gr0 + 16 <= N_NODES) {
#pragma unroll
            for (int j = 0; j < 4; ++j)
                wmma::store_matrix_sync(out + (size_t)gr0 * D_OUT + wn * 64 + j * 16,
                                        acc[i][j], D_OUT, wmma::mem_row_major);
        }
    }
}

// ---------------- launch ----------------
extern "C" void kernel_launch(void* const* d_in, const int* in_sizes, int n_in,
                              void* d_out, int out_size) {
    const float* input = nullptr;
    const float* fc_w  = nullptr;
    const float* fc_b  = nullptr;
    const float* w_out = nullptr;
    const int*   adj   = nullptr;
    for (int i = 0; i < n_in; ++i) {
        switch (in_sizes[i]) {
            case 6400000: input = (const float*)d_in[i]; break;
            case 65536:   fc_w  = (const float*)d_in[i]; break;
            case 512:     fc_b  = (const float*)d_in[i]; break;
            case 81920:   w_out = (const float*)d_in[i]; break;
            case 1600000: adj   = (const int*)d_in[i]; break;
            default: break;
        }
    }
    float* out = (float*)d_out;
    (void)out_size;
    if (!input || !fc_w || !fc_b || !w_out || !adj) return;

    // CSR build
    detect_kernel<<<1, 256>>>(adj);
    zero_counts_kernel<<<(N_NODES + 255) / 256, 256>>>();
    hist_kernel<<<(N_EDGES + 255) / 256, 256>>>(adj);
    blocksum_kernel<<<SCAN_NB, 256>>>();
    scanblock_kernel<<<1, 256>>>();
    offsets_kernel<<<SCAN_NB, 256>>>();
    scatter_kernel<<<(N_EDGES + 255) / 256, 256>>>(adj);

    // fp16 conversions
    conv_x_kernel<<<(N_NODES * D_IN / 8 + 255) / 256, 256>>>(input);
    conv_w_kernel<<<(D_CAT * D_OUT + 255) / 256, 256>>>(fc_w, w_out);

    // Z = relu(Xh @ Wh + b) on tensor cores
    dim3 gA(D_HID / 64, (N_NODES + 127) / 128);
    gemm_relu_wmma<<<gA, 256>>>(fc_b);

    // agg = segment_max(Z[trg], by src) -> g_cat[:,128:640]
    segmax_kernel<<<N_NODES, 128>>>();

    // out = g_cat @ W2 on tensor cores
    gemm_out_wmma<<<(N_NODES + 127) / 128, 256>>>(out);
}

// round 6
// speedup vs baseline: 3.2758x; 1.0821x over previous
#include <cuda_runtime.h>
#include <cuda_fp16.h>
#include <mma.h>
#include <cstdint>

using namespace nvcuda;

#define N_NODES 50000
#define N_EDGES 800000
#define D_IN    128
#define D_HID   512
#define D_OUT   128
#define D_CAT   (D_IN + D_HID)
#define SCAN_NB ((N_NODES + 255) / 256)   // 196

// ---------------- device scratch (no allocations allowed) ----------------
__device__ __align__(16) __half g_Zh[(size_t)N_NODES * D_HID];   // relu(x@W+b) fp16
__device__ __align__(16) __half g_cat[(size_t)N_NODES * D_CAT];  // [Xh | agg_h]
__device__ __align__(16) __half g_Wh[(size_t)D_IN * D_HID];      // fc_w fp16
__device__ __align__(16) __half g_W2h[(size_t)D_CAT * D_OUT];    // weights fp16
__device__ __align__(16) int    g_counts[N_NODES];
__device__ __align__(16) int    g_offsets[N_NODES + 1];
__device__ __align__(16) int    g_cursor[N_NODES];
__device__ __align__(16) int    g_elist[N_EDGES];
__device__ __align__(16) int    g_blocksums[256];
__device__ __align__(16) int    g_blockoff[256];
__device__ int g_is64;

// ---------------- detect adjacency dtype + zero counts (fused) ----------------
__global__ void detect_zero_kernel(const int* __restrict__ a) {
    int i = blockIdx.x * blockDim.x + threadIdx.x;
    if (i < N_NODES) g_counts[i] = 0;
    if (blockIdx.x == 0) {
        __shared__ int any;
        if (threadIdx.x == 0) any = 0;
        __syncthreads();
        int local = 0;
        for (int k = threadIdx.x; k < 4096; k += 256)
            if (a[2 * k + 1] != 0) local = 1;
        if (local) atomicOr(&any, 1);
        __syncthreads();
        if (threadIdx.x == 0) g_is64 = (any == 0);
    }
}

// ---------------- CSR build ----------------
__global__ void hist_kernel(const int* __restrict__ adj) {
    int e = blockIdx.x * blockDim.x + threadIdx.x;
    if (e < N_EDGES) {
        int src = g_is64 ? adj[2 * e] : adj[e];
        if ((unsigned)src < (unsigned)N_NODES)
            atomicAdd(&g_counts[src], 1);
    }
}

__global__ __launch_bounds__(256) void blocksum_kernel() {
    __shared__ int sm[256];
    int t = threadIdx.x;
    int i = blockIdx.x * 256 + t;
    sm[t] = (i < N_NODES) ? g_counts[i] : 0;
    __syncthreads();
    for (int off = 128; off > 0; off >>= 1) {
        if (t < off) sm[t] += sm[t + off];
        __syncthreads();
    }
    if (t == 0) g_blocksums[blockIdx.x] = sm[0];
}

__global__ __launch_bounds__(256) void scanblock_kernel() {
    __shared__ int sm[256];
    int t = threadIdx.x;
    int v = (t < SCAN_NB) ? g_blocksums[t] : 0;
    sm[t] = v;
    __syncthreads();
    for (int off = 1; off < 256; off <<= 1) {
        int x = (t >= off) ? sm[t - off] : 0;
        __syncthreads();
        sm[t] += x;
        __syncthreads();
    }
    if (t < SCAN_NB) g_blockoff[t] = sm[t] - v;
    if (t == 255) g_offsets[N_NODES] = sm[255];
}

__global__ __launch_bounds__(256) void offsets_kernel() {
    __shared__ int sm[256];
    int t = threadIdx.x;
    int i = blockIdx.x * 256 + t;
    int v = (i < N_NODES) ? g_counts[i] : 0;
    sm[t] = v;
    __syncthreads();
    for (int off = 1; off < 256; off <<= 1) {
        int x = (t >= off) ? sm[t - off] : 0;
        __syncthreads();
        sm[t] += x;
        __syncthreads();
    }
    if (i < N_NODES) {
        int excl = g_blockoff[blockIdx.x] + sm[t] - v;
        g_offsets[i] = excl;
        g_cursor[i]  = excl;
    }
}

__global__ void scatter_kernel(const int* __restrict__ adj) {
    int e = blockIdx.x * blockDim.x + threadIdx.x;
    if (e < N_EDGES) {
        int is64 = g_is64;
        int src = is64 ? adj[2 * e] : adj[e];
        int trg = is64 ? adj[2 * (N_EDGES + e)] : adj[N_EDGES + e];
        if ((unsigned)src < (unsigned)N_NODES && (unsigned)trg < (unsigned)N_NODES) {
            int pos = atomicAdd(&g_cursor[src], 1);
            if ((unsigned)pos < (unsigned)N_EDGES)
                g_elist[pos] = trg;
        }
    }
}

// ---------------- conversions to fp16 (X + both weight matrices) ----------------
#define CONV_X_VECS (N_NODES * D_IN / 8)             // 800000 uint4s
__global__ void conv_all_kernel(const float* __restrict__ X,
                                const float* __restrict__ fcw,
                                const float* __restrict__ w2) {
    int idx = blockIdx.x * blockDim.x + threadIdx.x;
    if (idx < CONV_X_VECS) {
        int i = idx * 8;
        int row = i >> 7;
        int col = i & 127;
        float4 a = *(const float4*)(X + i);
        float4 b = *(const float4*)(X + i + 4);
        union { __half h[8]; uint4 u; } pk;
        pk.h[0] = __float2half_rn(a.x); pk.h[1] = __float2half_rn(a.y);
        pk.h[2] = __float2half_rn(a.z); pk.h[3] = __float2half_rn(a.w);
        pk.h[4] = __float2half_rn(b.x); pk.h[5] = __float2half_rn(b.y);
        pk.h[6] = __float2half_rn(b.z); pk.h[7] = __float2half_rn(b.w);
        *(uint4*)(g_cat + (size_t)row * D_CAT + col) = pk.u;
    }
    if (idx < D_IN * D_HID) g_Wh[idx] = __float2half_rn(fcw[idx]);
    if (idx < D_CAT * D_OUT) g_W2h[idx] = __float2half_rn(w2[idx]);
}

// ---------------- Z = relu(Xh @ Wh + b) via wmma -> fp16 ----------------
// BM=128, BN=64, BK=32, 8 warps as 4(M)x2(N), warp tile 32x32.
__global__ __launch_bounds__(256) void gemm_relu_wmma(const float* __restrict__ bias) {
    __shared__ union SMem {
        struct { __half A[128 * 40]; __half B[32 * 72]; } t;
        float C[8 * 32 * 36];
    } sm;

    const int bm = blockIdx.y * 128;
    const int bn = blockIdx.x * 64;
    const int tid = threadIdx.x;
    const int warp = tid >> 5;
    const int lane = tid & 31;
    const int wm = warp >> 1;     // 0..3
    const int wn = warp & 1;      // 0..1

    wmma::fragment<wmma::accumulator, 16, 16, 16, float> acc[2][2];
#pragma unroll
    for (int i = 0; i < 2; ++i)
#pragma unroll
        for (int j = 0; j < 2; ++j) wmma::fill_fragment(acc[i][j], 0.f);

    for (int k0 = 0; k0 < D_IN; k0 += 32) {
#pragma unroll
        for (int r = 0; r < 2; ++r) {
            int f = tid + r * 256;
            int row = f >> 2, seg = f & 3;
            int gr = bm + row; if (gr >= N_NODES) gr = N_NODES - 1;
            *(uint4*)&sm.t.A[row * 40 + seg * 8] =
                *(const uint4*)(g_cat + (size_t)gr * D_CAT + k0 + seg * 8);
        }
        {
            int row = tid >> 3, seg = tid & 7;
            *(uint4*)&sm.t.B[row * 72 + seg * 8] =
                *(const uint4*)(g_Wh + (size_t)(k0 + row) * D_HID + bn + seg * 8);
        }
        __syncthreads();
#pragma unroll
        for (int kk = 0; kk < 2; ++kk) {
            wmma::fragment<wmma::matrix_a, 16, 16, 16, __half, wmma::row_major> af[2];
            wmma::fragment<wmma::matrix_b, 16, 16, 16, __half, wmma::row_major> bf[2];
#pragma unroll
            for (int i = 0; i < 2; ++i)
                wmma::load_matrix_sync(af[i], &sm.t.A[(wm * 32 + i * 16) * 40 + kk * 16], 40);
#pragma unroll
            for (int j = 0; j < 2; ++j)
                wmma::load_matrix_sync(bf[j], &sm.t.B[(kk * 16) * 72 + wn * 32 + j * 16], 72);
#pragma unroll
            for (int i = 0; i < 2; ++i)
#pragma unroll
                for (int j = 0; j < 2; ++j)
                    wmma::mma_sync(acc[i][j], af[i], bf[j], acc[i][j]);
        }
        __syncthreads();
    }

    // epilogue via per-warp smem staging
    float* cw = &sm.C[warp * 32 * 36];
#pragma unroll
    for (int i = 0; i < 2; ++i)
#pragma unroll
        for (int j = 0; j < 2; ++j)
            wmma::store_matrix_sync(&cw[(i * 16) * 36 + j * 16], acc[i][j], 36, wmma::mem_row_major);
    __syncwarp();

    int r = lane;
    int gr = bm + wm * 32 + r;
    if (gr < N_NODES) {
        int cbase = bn + wn * 32;
        union { __half h[8]; uint4 u; } pk;
#pragma unroll
        for (int q = 0; q < 4; ++q) {
#pragma unroll
            for (int c = 0; c < 8; ++c) {
                int col = q * 8 + c;
                float v = cw[r * 36 + col] + bias[cbase + col];
                pk.h[c] = __float2half_rn(fmaxf(v, 0.f));
            }
            *(uint4*)(g_Zh + (size_t)gr * D_HID + cbase + q * 8) = pk.u;
        }
    }
}

// ---------------- segment max over CSR -> fp16 into g_cat[:,128:640] ----------------
__global__ __launch_bounds__(128) void segmax_kernel() {
    int n = blockIdx.x;
    int t = threadIdx.x;
    int beg = g_offsets[n];
    int end = g_offsets[n + 1];

    __half2 m0 = __float2half2_rn(0.f);
    __half2 m1 = __float2half2_rn(0.f);

    int i = beg;
    for (; i + 3 < end; i += 4) {
        int e0 = g_elist[i + 0];
        int e1 = g_elist[i + 1];
        int e2 = g_elist[i + 2];
        int e3 = g_elist[i + 3];
        uint2 v0 = *(const uint2*)(g_Zh + (size_t)e0 * D_HID + t * 4);
        uint2 v1 = *(const uint2*)(g_Zh + (size_t)e1 * D_HID + t * 4);
        uint2 v2 = *(const uint2*)(g_Zh + (size_t)e2 * D_HID + t * 4);
        uint2 v3 = *(const uint2*)(g_Zh + (size_t)e3 * D_HID + t * 4);
        m0 = __hmax2(m0, *(const __half2*)&v0.x);
        m1 = __hmax2(m1, *(const __half2*)&v0.y);
        m0 = __hmax2(m0, *(const __half2*)&v1.x);
        m1 = __hmax2(m1, *(const __half2*)&v1.y);
        m0 = __hmax2(m0, *(const __half2*)&v2.x);
        m1 = __hmax2(m1, *(const __half2*)&v2.y);
        m0 = __hmax2(m0, *(const __half2*)&v3.x);
        m1 = __hmax2(m1, *(const __half2*)&v3.y);
    }
    for (; i < end; ++i) {
        int e0 = g_elist[i];
        uint2 v0 = *(const uint2*)(g_Zh + (size_t)e0 * D_HID + t * 4);
        m0 = __hmax2(m0, *(const __half2*)&v0.x);
        m1 = __hmax2(m1, *(const __half2*)&v0.y);
    }

    uint2 o;
    *(__half2*)&o.x = m0;
    *(__half2*)&o.y = m1;
    *(uint2*)(g_cat + (size_t)n * D_CAT + D_IN + t * 4) = o;
}

// ---------------- out = g_cat @ W2h via wmma (fp32 out) ----------------
// BM=128, BN=128, BK=32, 8 warps 4(M)x2(N), warp tile 32x64.
__global__ __launch_bounds__(256) void gemm_out_wmma(float* __restrict__ out) {
    __shared__ __half As[128 * 40];
    __shared__ __half Bs[32 * 136];

    const int bm = blockIdx.x * 128;
    const int tid = threadIdx.x;
    const int warp = tid >> 5;
    const int wm = warp >> 1;
    const int wn = warp & 1;

    wmma::fragment<wmma::accumulator, 16, 16, 16, float> acc[2][4];
#pragma unroll
    for (int i = 0; i < 2; ++i)
#pragma unroll
        for (int j = 0; j < 4; ++j) wmma::fill_fragment(acc[i][j], 0.f);

    for (int k0 = 0; k0 < D_CAT; k0 += 32) {
#pragma unroll
        for (int r = 0; r < 2; ++r) {
            int f = tid + r * 256;
            int row = f >> 2, seg = f & 3;
            int gr = bm + row; if (gr >= N_NODES) gr = N_NODES - 1;
            *(uint4*)&As[row * 40 + seg * 8] =
                *(const uint4*)(g_cat + (size_t)gr * D_CAT + k0 + seg * 8);
        }
#pragma unroll
        for (int r = 0; r < 2; ++r) {
            int f = tid + r * 256;
            int row = f >> 4, seg = f & 15;
            *(uint4*)&Bs[row * 136 + seg * 8] =
                *(const uint4*)(g_W2h + (size_t)(k0 + row) * D_OUT + seg * 8);
        }
        __syncthreads();
#pragma unroll
        for (int kk = 0; kk < 2; ++kk) {
            wmma::fragment<wmma::matrix_a, 16, 16, 16, __half, wmma::row_major> af[2];
            wmma::fragment<wmma::matrix_b, 16, 16, 16, __half, wmma::row_major> bf[4];
#pragma unroll
            for (int i = 0; i < 2; ++i)
                wmma::load_matrix_sync(af[i], &As[(wm * 32 + i * 16) * 40 + kk * 16], 40);
#pragma unroll
            for (int j = 0; j < 4; ++j)
                wmma::load_matrix_sync(bf[j], &Bs[(kk * 16) * 136 + wn * 64 + j * 16], 136);
#pragma unroll
            for (int i = 0; i < 2; ++i)
#pragma unroll
                for (int j = 0; j < 4; ++j)
                    wmma::mma_sync(acc[i][j], af[i], bf[j], acc[i][j]);
        }
        __syncthreads();
    }

#pragma unroll
    for (int i = 0; i < 2; ++i) {
        int gr0 = bm + wm * 32 + i * 16;
        if (gr0 + 16 <= N_NODES) {
#pragma unroll
            for (int j = 0; j < 4; ++j)
                wmma::store_matrix_sync(out + (size_t)gr0 * D_OUT + wn * 64 + j * 16,
                                        acc[i][j], D_OUT, wmma::mem_row_major);
        }
    }
}

// ---------------- launch ----------------
extern "C" void kernel_launch(void* const* d_in, const int* in_sizes, int n_in,
                              void* d_out, int out_size) {
    const float* input = nullptr;
    const float* fc_w  = nullptr;
    const float* fc_b  = nullptr;
    const float* w_out = nullptr;
    const int*   adj   = nullptr;
    for (int i = 0; i < n_in; ++i) {
        switch (in_sizes[i]) {
            case 6400000: input = (const float*)d_in[i]; break;
            case 65536:   fc_w  = (const float*)d_in[i]; break;
            case 512:     fc_b  = (const float*)d_in[i]; break;
            case 81920:   w_out = (const float*)d_in[i]; break;
            case 1600000: adj   = (const int*)d_in[i]; break;
            default: break;
        }
    }
    float* out = (float*)d_out;
    (void)out_size;
    if (!input || !fc_w || !fc_b || !w_out || !adj) return;

    // Fork: CSR build on a side stream, conversions + Z-GEMM on the main stream.
    cudaStream_t sCSR;
    cudaStreamCreateWithFlags(&sCSR, cudaStreamNonBlocking);
    cudaEvent_t evFork, evJoin;
    cudaEventCreateWithFlags(&evFork, cudaEventDisableTiming);
    cudaEventCreateWithFlags(&evJoin, cudaEventDisableTiming);

    cudaEventRecord(evFork, 0);
    cudaStreamWaitEvent(sCSR, evFork, 0);

    // --- side stream: CSR build ---
    detect_zero_kernel<<<(N_NODES + 255) / 256, 256, 0, sCSR>>>(adj);
    hist_kernel<<<(N_EDGES + 255) / 256, 256, 0, sCSR>>>(adj);
    blocksum_kernel<<<SCAN_NB, 256, 0, sCSR>>>();
    scanblock_kernel<<<1, 256, 0, sCSR>>>();
    offsets_kernel<<<SCAN_NB, 256, 0, sCSR>>>();
    scatter_kernel<<<(N_EDGES + 255) / 256, 256, 0, sCSR>>>(adj);
    cudaEventRecord(evJoin, sCSR);

    // --- main stream: fp16 conversions + Z GEMM ---
    conv_all_kernel<<<(CONV_X_VECS + 255) / 256, 256>>>(input, fc_w, w_out);
    dim3 gA(D_HID / 64, (N_NODES + 127) / 128);
    gemm_relu_wmma<<<gA, 256>>>(fc_b);

    // join, then segmax + out GEMM
    cudaStreamWaitEvent(0, evJoin, 0);
    segmax_kernel<<<N_NODES, 128>>>();
    gemm_out_wmma<<<(N_NODES + 127) / 128, 256>>>(out);

    cudaEventDestroy(evFork);
    cudaEventDestroy(evJoin);
    cudaStreamDestroy(sCSR);
}